// round 9
// baseline (speedup 1.0000x reference)
#include <cuda_runtime.h>
#include <cuda_bf16.h>

#define T_STEPS 131072
#define DTF (1.0f / 262.0f)
#define ETA_F     1e-6f
#define TWO_ETA_F 2e-6f

typedef unsigned long long u64;

// ---- f32x2 packed helpers (FFMA2/FMUL2/FADD2: one FMA-pipe slot, two lanes) ----
__device__ __forceinline__ u64 pk2(float lo, float hi) {
    u64 r; asm("mov.b64 %0, {%1, %2};" : "=l"(r) : "f"(lo), "f"(hi)); return r;
}
__device__ __forceinline__ void upk2(float& lo, float& hi, u64 v) {
    asm("mov.b64 {%0, %1}, %2;" : "=f"(lo), "=f"(hi) : "l"(v));
}
__device__ __forceinline__ u64 f2fma(u64 a, u64 b, u64 c) {
    u64 d; asm("fma.rn.f32x2 %0, %1, %2, %3;" : "=l"(d) : "l"(a), "l"(b), "l"(c)); return d;
}
__device__ __forceinline__ u64 f2mul(u64 a, u64 b) {
    u64 d; asm("mul.rn.f32x2 %0, %1, %2;" : "=l"(d) : "l"(a), "l"(b)); return d;
}
__device__ __forceinline__ u64 f2add(u64 a, u64 b) {
    u64 d; asm("add.rn.f32x2 %0, %1, %2;" : "=l"(d) : "l"(a), "l"(b)); return d;
}

// Packed per-step inputs: {obs, kap*softplus(theta+garch), carma0, carma1}
__device__ float4 g_pack[T_STEPS];

__global__ void pack_kernel(const float* __restrict__ obs,
                            const float* __restrict__ garch,
                            const float* __restrict__ carma,
                            const float* __restrict__ kappa,
                            const float* __restrict__ theta) {
    int t = blockIdx.x * blockDim.x + threadIdx.x;
    if (t < T_STEPS) {
        float kap = log1pf(expf(kappa[0]));
        float th  = log1pf(expf(theta[0] + garch[t]));
        g_pack[t] = make_float4(obs[t], kap * th, carma[2 * t], carma[2 * t + 1]);
    }
}

__global__ void __launch_bounds__(32, 1) scan_kernel(
    const float* __restrict__ w0v, const float* __restrict__ P0,
    const float* __restrict__ b0p, const float* __restrict__ b1p,
    const float* __restrict__ a1p, const float* __restrict__ kappap,
    const float* __restrict__ xip, const float* __restrict__ rhop,
    float4* __restrict__ out) {
    if (threadIdx.x != 0) return;

    float kap  = log1pf(expf(kappap[0]));
    float xi_  = log1pf(expf(xip[0]));
    float rho_ = tanhf(rhop[0]);
    float xi2  = xi_ * xi_;
    float a1   = a1p[0];
    float f1   = b0p[0] * DTF;
    float f2   = b1p[0] * DTF;
    float dd   = 1.0f - a1 * DTF;
    float ddsq = dd * dd;
    float C0DT = (0.5f * xi2 - kap) * DTF;    // (xi^2/2 - kap)*DT
    float R00c = fmaf(xi2, DTF, TWO_ETA_F);   // xi^2*DT + 2eta
    float xrDT = xi_ * rho_ * DTF;            // cross*DT = S * xrDT

    // Packed constants
    const u64 DTV   = pk2(DTF, DTF);
    const u64 ONEA1 = pk2(1.0f, -a1);
    const u64 F1V   = pk2(f1, f1);
    const u64 F2V   = pk2(f2, f2);
    const u64 ETAV  = pk2(ETA_F, ETA_F);

    // State (w1,w2) and (p00,p22) live permanently packed
    float w0 = w0v[0];
    u64   WW = pk2(w0v[1], w0v[2]);
    float p01 = P0[1], p02 = P0[2];
    float p11 = P0[4], p12 = P0[5], p22 = P0[8];
    u64   PD  = pk2(P0[0], P0[8]);

    // Carried exponentials of w0 + carried 1/Q
    float E  = __expf(w0);
    float En = __expf(-w0);
    float S  = __expf(0.5f * w0);
    u64   EE = pk2(E, En);
    float rq = 1.0f / fmaf(E, DTF, TWO_ETA_F);

    // Software-pipelined input ring (prefetch depth 8)
    float4 buf[8];
#pragma unroll
    for (int i = 0; i < 8; i++) buf[i] = g_pack[i];

    for (int t = 0; t < T_STEPS; t += 8) {
        if ((t & 1023) == 0) {      // periodic exact resync (kills poly drift)
            E  = __expf(w0);
            En = __expf(-w0);
            S  = __expf(0.5f * w0);
            EE = pk2(E, En);
        }
#pragma unroll
        for (int j = 0; j < 8; j++) {
            float4 d = buf[j];
            int nt = t + 8 + j;
            if (nt < T_STEPS) buf[j] = g_pack[nt];

            float obs = d.x, kth = d.y;

            // --- predict (spine) ---
            float term = kth * fminf(En, 1.0f);       // kth*clip(exp(-w0),0,1)
            float dw1  = fmaf(term, DTF, C0DT);
            float a    = 1.0f - term;
            float w0p  = w0 + dw1;

            // (w1p, w2p) = ( (w2+c0)*DT + w1 , (-a1*w2+c1)*DT + w2 )
            float w1c, w2c; upk2(w1c, w2c, WW);
            u64 tw  = f2fma(pk2(w2c, w2c), ONEA1, pk2(d.z, d.w));
            u64 WWp = f2fma(tw, DTV, WW);
            float w1p, w2p; upk2(w1p, w2p, WWp);

            // --- P_pred (Psi = diag(a,1,dd), Psi[1,2]=DT) ---
            // (p01p, p12p) = ( a*(DT*p02+p01) , dd*(DT*p22+p12) )
            u64 o1 = f2mul(f2fma(pk2(p02, p22), DTV, pk2(p01, p12)), pk2(a, dd));
            float p01p, p12p; upk2(p01p, p12p, o1);

            float t11  = fmaf(p22, DTF, p12 + p12);
            float p11p = fmaf(t11, DTF, p11) + TWO_ETA_F;
            float p02p = fmaf(a * dd, p02, S * xrDT);

            float aa   = a * a;
            float e22c = fmaf(E, DTF, TWO_ETA_F);
            u64 PDp = f2fma(pk2(aa, ddsq), PD, pk2(R00c, e22c));   // (p00p,p22p)
            float p00p_, p22p; upk2(p00p_, p22p, PDp);

            // --- update ---
            float sig2p = E * fmaf(dw1, fmaf(dw1, 0.5f, 1.0f), 1.0f);
            u64 U01 = f2fma(pk2(p01p, p11p), F1V, f2mul(pk2(p02p, p12p), F2V));
            float u0, u1; upk2(u0, u1, U01);
            float u2 = fmaf(f1, p12p, f2 * p22p);
            float Q  = fmaf(f1, u1, fmaf(f2, u2, fmaf(sig2p, DTF, TWO_ETA_F)));
            rq = rq * fmaf(-Q, rq, 2.0f);             // Newton: rq <- rq(2-Q*rq)

            float xp = fmaf(f1, w1p, f2 * w2p);
            float g  = (obs - xp) * rq;

            w0 = fmaf(u0, g, w0p);
            u64 U12 = pk2(u1, u2);
            WW = f2fma(U12, pk2(g, g), WWp);

            float nrq = -rq;
            float ns0 = u0 * nrq, ns1 = u1 * nrq, ns2 = u2 * nrq;
            u64 PB = f2fma(pk2(ns0, ns0), U12, pk2(p01p, p02p));
            upk2(p01, p02, PB);
            u64 PC = f2fma(pk2(ns1, ns1), U12, pk2(p11p, p12p));
            upk2(p11, p12, PC);
            p11 += ETA_F;
            PD = f2add(f2fma(pk2(ns0, ns2), pk2(u0, u2), PDp), ETAV);
            float p00s; upk2(p00s, p22, PD);

            // --- carried exponentials: multiply by exp(+/-dw) Taylor ---
            float dw   = fmaf(u0, g, dw1);
            float dw2  = dw * dw;
            float even = fmaf(dw2, 0.5f, 1.0f);
            float odd  = dw * fmaf(dw2, 0.16666667f, 1.0f);
            EE = f2mul(EE, f2add(pk2(even, even), pk2(odd, -odd)));
            upk2(E, En, EE);
            S  = S * fmaf(dw, fmaf(dw, 0.125f, 0.5f), 1.0f);

            float w1n, w2n; upk2(w1n, w2n, WW);
            out[t + j] = make_float4(xp, w0, w1n, w2n);
        }
    }
}

extern "C" void kernel_launch(void* const* d_in, const int* in_sizes, int n_in,
                              void* d_out, int out_size) {
    const float* obs   = (const float*)d_in[0];
    const float* garch = (const float*)d_in[1];
    const float* carma = (const float*)d_in[2];
    const float* w0v   = (const float*)d_in[3];
    const float* P0    = (const float*)d_in[4];
    const float* b0    = (const float*)d_in[5];
    const float* b1    = (const float*)d_in[6];
    const float* a1    = (const float*)d_in[7];
    const float* kappa = (const float*)d_in[8];
    const float* theta = (const float*)d_in[9];
    const float* xi    = (const float*)d_in[10];
    const float* rho   = (const float*)d_in[11];
    float4* out = (float4*)d_out;

    pack_kernel<<<(T_STEPS + 255) / 256, 256>>>(obs, garch, carma, kappa, theta);
    scan_kernel<<<1, 32>>>(w0v, P0, b0, b1, a1, kappa, xi, rho, out);
}

// round 11
// speedup vs baseline: 1.2841x; 1.2841x over previous
#include <cuda_runtime.h>
#include <cuda_bf16.h>

#define T_STEPS 131072
#define DTF       (1.0f / 262.0f)
#define DT2F      (DTF * DTF)
#define TWO_DTF   (2.0f * DTF)
#define ETA_F     1e-6f
#define TWO_ETA_F 2e-6f

// Packed per-step inputs: {obs, kap*softplus(theta+garch), carma0, carma1}
__device__ float4 g_pack[T_STEPS];

__global__ void pack_kernel(const float* __restrict__ obs,
                            const float* __restrict__ garch,
                            const float* __restrict__ carma,
                            const float* __restrict__ kappa,
                            const float* __restrict__ theta) {
    int t = blockIdx.x * blockDim.x + threadIdx.x;
    if (t < T_STEPS) {
        float kap = log1pf(expf(kappa[0]));
        float th  = log1pf(expf(theta[0] + garch[t]));
        g_pack[t] = make_float4(obs[t], kap * th, carma[2 * t], carma[2 * t + 1]);
    }
}

__global__ void __launch_bounds__(32, 1) scan_kernel(
    const float* __restrict__ w0v, const float* __restrict__ P0,
    const float* __restrict__ b0p, const float* __restrict__ b1p,
    const float* __restrict__ a1p, const float* __restrict__ kappap,
    const float* __restrict__ xip, const float* __restrict__ rhop,
    float4* __restrict__ out) {
    if (threadIdx.x != 0) return;

    float kap  = log1pf(expf(kappap[0]));
    float xi_  = log1pf(expf(xip[0]));
    float rho_ = tanhf(rhop[0]);
    float xi2  = xi_ * xi_;
    float a1   = a1p[0];
    float f1   = b0p[0] * DTF;
    float f2   = b1p[0] * DTF;
    float dd   = 1.0f - a1 * DTF;
    float ddsq = dd * dd;
    float C0DT = (0.5f * xi2 - kap) * DTF;      // (xi^2/2 - kap)*DT
    float xrDT = xi_ * rho_ * DTF;              // cross*DT = S * xrDT

    // Exact eta-fold constants (posterior +eta*I absorbed into next predict):
    float P11C = 3.0f * ETA_F + DT2F * ETA_F;   // p11p constant
    float P12C = dd * DTF * ETA_F;              // p12p constant
    float E22C = fmaf(ddsq, ETA_F, TWO_ETA_F);  // p22p constant (+ E*DT at runtime)

    // State. NOTE: p00 is provably dead w.r.t. outputs (x, w) — eliminated.
    // p11/p22 are carried WITHOUT their posterior +eta (folded into consts).
    float w0 = w0v[0], w1 = w0v[1], w2 = w0v[2];
    float p01 = P0[1], p02 = P0[2];
    float p11 = P0[4], p12 = P0[5], p22 = P0[8];

    // Carried exponentials of w0 + carried cross-term + carried 1/Q
    float E  = __expf(w0);                  // exp(w0)  (sigma^2)
    float En = __expf(-w0);                 // exp(-w0)
    float CS = __expf(0.5f * w0) * xrDT;    // sigma * xi * rho * DT
    float rq = 1.0f / fmaf(E, DTF, TWO_ETA_F);

    // Software-pipelined input ring (prefetch depth 8)
    float4 buf[8];
#pragma unroll
    for (int i = 0; i < 8; i++) buf[i] = g_pack[i];

    for (int t = 0; t < T_STEPS; t += 8) {
        if ((t & 511) == 0) {   // periodic exact resync (kills Taylor drift)
            E  = __expf(w0);
            En = __expf(-w0);
            CS = __expf(0.5f * w0) * xrDT;
        }
#pragma unroll
        for (int j = 0; j < 8; j++) {
            float4 d = buf[j];
            int nt = t + 8 + j;
            if (nt < T_STEPS) buf[j] = g_pack[nt];

            float obs = d.x, kth = d.y, c0 = d.z, c1 = d.w;

            // --- predict ---
            float term = kth * fminf(En, 1.0f);     // kth*clip(exp(-w0),0,1)
            float dw1  = fmaf(term, DTF, C0DT);
            float a    = 1.0f - term;
            float w0p  = w0 + dw1;
            float w1p  = fmaf(w2 + c0, DTF, w1);
            float w2p  = fmaf(fmaf(-a1, w2, c1), DTF, w2);

            // P_pred (Psi = diag(a,1,dd) with Psi[1,2]=DT); p00 dropped.
            float p01p = a * fmaf(p02, DTF, p01);
            float p02p = fmaf(a * dd, p02, CS);
            float p11p = fmaf(p22, DT2F, fmaf(p12, TWO_DTF, P11C)) + p11;
            float p12p = fmaf(dd, fmaf(p22, DTF, p12), P12C);
            float p22p = fmaf(ddsq, p22, fmaf(E, DTF, E22C));

            // --- update ---
            float sig2p = E * fmaf(dw1, fmaf(dw1, 0.5f, 1.0f), 1.0f);
            float u0 = fmaf(f1, p01p, f2 * p02p);
            float u1 = fmaf(f1, p11p, f2 * p12p);
            float u2 = fmaf(f1, p12p, f2 * p22p);
            float Q  = fmaf(f1, u1, fmaf(f2, u2, fmaf(sig2p, DTF, TWO_ETA_F)));
            rq = rq * fmaf(-Q, rq, 2.0f);           // Newton: rq <- rq(2-Q*rq)

            float xp    = fmaf(f1, w1p, f2 * w2p);
            float innov = obs - xp;
            float K0 = u0 * rq, K1 = u1 * rq, K2 = u2 * rq;

            w0 = fmaf(K0, innov, w0p);
            w1 = fmaf(K1, innov, w1p);
            w2 = fmaf(K2, innov, w2p);

            p01 = fmaf(-K0, u1, p01p);
            p02 = fmaf(-K0, u2, p02p);
            p11 = fmaf(-K1, u1, p11p);
            p12 = fmaf(-K1, u2, p12p);
            p22 = fmaf(-K2, u2, p22p);

            // --- carried exponentials: quadratic Taylor of exp(+/-dw) ---
            float dw   = fmaf(K0, innov, dw1);
            float dwsq = dw * dw;
            float even = fmaf(dwsq, 0.5f, 1.0f);
            E  = E  * (even + dw);
            En = En * (even - dw);
            CS = CS * fmaf(dw, fmaf(dw, 0.125f, 0.5f), 1.0f);   // *exp(dw/2)

            out[t + j] = make_float4(xp, w0, w1, w2);
        }
    }
}

extern "C" void kernel_launch(void* const* d_in, const int* in_sizes, int n_in,
                              void* d_out, int out_size) {
    const float* obs   = (const float*)d_in[0];
    const float* garch = (const float*)d_in[1];
    const float* carma = (const float*)d_in[2];
    const float* w0v   = (const float*)d_in[3];
    const float* P0    = (const float*)d_in[4];
    const float* b0    = (const float*)d_in[5];
    const float* b1    = (const float*)d_in[6];
    const float* a1    = (const float*)d_in[7];
    const float* kappa = (const float*)d_in[8];
    const float* theta = (const float*)d_in[9];
    const float* xi    = (const float*)d_in[10];
    const float* rho   = (const float*)d_in[11];
    float4* out = (float4*)d_out;

    pack_kernel<<<(T_STEPS + 255) / 256, 256>>>(obs, garch, carma, kappa, theta);
    scan_kernel<<<1, 32>>>(w0v, P0, b0, b1, a1, kappa, xi, rho, out);
}